// round 7
// baseline (speedup 1.0000x reference)
#include <cuda_runtime.h>

#define EDGES   65536
#define NODESN  2048
#define DI      64
#define DOUT    64
#define EPSV    1e-6f
#define RCHUNK  16             // rows per scan tile (8192 tiles -> ~99% slot util)
#define CAP     256            // adjacency capacity per node (deg ~ Binom, mean 32)

// scratch (no cudaMalloc allowed)
__device__ int   g_si[EDGES];          // src index per edge
__device__ int   g_cnt[NODESN];        // per-target edge count (reset by gather)
__device__ int   g_adj[NODESN * CAP];  // per-target edge lists
__device__ float g_P[NODESN * DOUT];   // x @ Wf_top
__device__ float g_Q[NODESN * DOUT];   // x @ Wf_bot
__device__ float g_u[NODESN];          // x . Ww_top
__device__ float g_v[NODESN];          // x . Ww_bot

// ---------------------------------------------------------------------------
// K0 (k_pre): per-node projections P,Q,u,v. Runs on a side stream fully
// overlapped with the HBM-bound scan (no shared state with it).
// 32 blocks x 256 threads; Wf in smem (32KB), x tile transposed (16KB).
// ---------------------------------------------------------------------------
__global__ void __launch_bounds__(256) k_pre(const float* __restrict__ x,
                                             const float* __restrict__ Wf,
                                             const float* __restrict__ Ww) {
    __shared__ float sW[2 * DI * DOUT];   // sW[k*64 + d], 32 KB
    __shared__ float sx[DI * 64];         // sx[k*64 + nl] (transposed), 16 KB

    const int tid = threadIdx.x;
    const int n0 = blockIdx.x * 64;

    // load Wf into smem: 2048 float4, 8 per thread
    {
        const float4* Wf4 = (const float4*)Wf;
        float4* sW4 = (float4*)sW;
#pragma unroll
        for (int i = 0; i < 8; ++i)
            sW4[tid + i * 256] = Wf4[tid + i * 256];
    }
    // load x tile transposed: 1024 float4 reads, scatter to sx[k][nl]
    {
        const float4* x4 = (const float4*)x;
#pragma unroll
        for (int i = 0; i < 4; ++i) {
            int idx = tid + i * 256;          // 0..1023
            int nl = idx >> 4;                // node local
            int kq = idx & 15;                // float4 group within row
            float4 vv = x4[(n0 + nl) * (DI / 4) + kq];
            sx[(kq * 4 + 0) * 64 + nl] = vv.x;
            sx[(kq * 4 + 1) * 64 + nl] = vv.y;
            sx[(kq * 4 + 2) * 64 + nl] = vv.z;
            sx[(kq * 4 + 3) * 64 + nl] = vv.w;
        }
    }
    __syncthreads();

    const int nl = tid >> 2;          // 0..63
    const int dg = (tid & 3) * 16;    // dim base

    float accP[16] = {}, accQ[16] = {};
    const float4* sW4 = (const float4*)sW;
#pragma unroll 4
    for (int k = 0; k < DI; ++k) {
        float xv = sx[k * 64 + nl];
        int bP = (k * DOUT + dg) >> 2;
        int bQ = ((DI + k) * DOUT + dg) >> 2;
#pragma unroll
        for (int j = 0; j < 4; ++j) {
            float4 w = sW4[bP + j];
            accP[j * 4 + 0] += xv * w.x; accP[j * 4 + 1] += xv * w.y;
            accP[j * 4 + 2] += xv * w.z; accP[j * 4 + 3] += xv * w.w;
            float4 q = sW4[bQ + j];
            accQ[j * 4 + 0] += xv * q.x; accQ[j * 4 + 1] += xv * q.y;
            accQ[j * 4 + 2] += xv * q.z; accQ[j * 4 + 3] += xv * q.w;
        }
    }
    float4* P4 = (float4*)(g_P + (n0 + nl) * DOUT + dg);
    float4* Q4 = (float4*)(g_Q + (n0 + nl) * DOUT + dg);
#pragma unroll
    for (int j = 0; j < 4; ++j) {
        P4[j] = make_float4(accP[j*4+0], accP[j*4+1], accP[j*4+2], accP[j*4+3]);
        Q4[j] = make_float4(accQ[j*4+0], accQ[j*4+1], accQ[j*4+2], accQ[j*4+3]);
    }

    // u, v: one thread per node
    if (tid < 64) {
        float uu = 0.f, vv = 0.f;
#pragma unroll 8
        for (int k = 0; k < DI; ++k) {
            float xv = sx[k * 64 + tid];
            uu += xv * __ldg(&Ww[k]);
            vv += xv * __ldg(&Ww[DI + k]);
        }
        g_u[n0 + tid] = uu;
        g_v[n0 + tid] = vv;
    }
}

// ---------------------------------------------------------------------------
// K1 (k_scan): one-hot -> indices + target-CSR, full 1 GB float4 stream.
// acc = sum (n+1)*v  ->  presence = (acc > 0.5), index = acc - 1 (exact fp32).
// src hit: store g_si[e]. tgt hit: append e to g_adj[t] (int atomic on g_cnt,
// hidden under the HBM stream). grid (64, 128) = 8192 tiles.
// ---------------------------------------------------------------------------
__global__ void __launch_bounds__(256) k_scan(const float4* __restrict__ src4,
                                              const float4* __restrict__ tgt4) {
    const int g4 = blockIdx.x * blockDim.x + threadIdx.x;   // 0..16383
    const int r0 = blockIdx.y * RCHUNK;
    const int stride4 = EDGES / 4;                          // 16384
    size_t base = (size_t)r0 * stride4 + g4;

    float4 ws = {0.f,0.f,0.f,0.f}, wt = {0.f,0.f,0.f,0.f};

#pragma unroll
    for (int n = 0; n < RCHUNK; ++n) {
        float fn1 = (float)(r0 + n + 1);
        float4 vs = __ldcs(&src4[base]);
        float4 vt = __ldcs(&tgt4[base]);
        base += stride4;
        ws.x += vs.x * fn1; ws.y += vs.y * fn1; ws.z += vs.z * fn1; ws.w += vs.w * fn1;
        wt.x += vt.x * fn1; wt.y += vt.y * fn1; wt.z += vt.z * fn1; wt.w += vt.w * fn1;
    }
    int e0 = g4 * 4;
    if (ws.x > 0.5f) g_si[e0 + 0] = (int)(ws.x - 0.5f);
    if (ws.y > 0.5f) g_si[e0 + 1] = (int)(ws.y - 0.5f);
    if (ws.z > 0.5f) g_si[e0 + 2] = (int)(ws.z - 0.5f);
    if (ws.w > 0.5f) g_si[e0 + 3] = (int)(ws.w - 0.5f);
    if (wt.x > 0.5f) { int t = (int)(wt.x - 0.5f);
        g_adj[t * CAP + atomicAdd(&g_cnt[t], 1)] = e0 + 0; }
    if (wt.y > 0.5f) { int t = (int)(wt.y - 0.5f);
        g_adj[t * CAP + atomicAdd(&g_cnt[t], 1)] = e0 + 1; }
    if (wt.z > 0.5f) { int t = (int)(wt.z - 0.5f);
        g_adj[t * CAP + atomicAdd(&g_cnt[t], 1)] = e0 + 2; }
    if (wt.w > 0.5f) { int t = (int)(wt.w - 0.5f);
        g_adj[t * CAP + atomicAdd(&g_cnt[t], 1)] = e0 + 3; }
}

// ---------------------------------------------------------------------------
// K2 (k_gather): warp = target node t, lane = 2 output dims.
// Loops the node's edge list: ae = exp(u[s]+v[t]+bw);
// acc += ae * relu(P[s]+Q[t]+bf); asum += ae. Writes out = acc/(asum+eps)
// directly (no float atomics, no div pass). Resets g_cnt for the next replay.
// No mean subtraction (softmax shift-invariant; EPS perturbation ~2e-8 rel).
// ---------------------------------------------------------------------------
__global__ void __launch_bounds__(256) k_gather(const float* __restrict__ bf,
                                                const float* __restrict__ bw,
                                                float* __restrict__ out) {
    const int t    = (blockIdx.x * blockDim.x + threadIdx.x) >> 5;  // node
    const int lane = threadIdx.x & 31;
    const int deg  = g_cnt[t];

    float2 q = ((const float2*)g_Q)[t * 32 + lane];
    float2 b = __ldg(&((const float2*)bf)[lane]);
    float  c = q.x + b.x;    // fold per-warp constants
    float  d = q.y + b.y;
    float  vt = g_v[t] + __ldg(bw);

    float2 acc = make_float2(0.f, 0.f);
    float  asum = 0.f;
    const int* adj = g_adj + t * CAP;

    for (int i = 0; i < deg; ++i) {
        int e = adj[i];                       // broadcast load
        int s = g_si[e];
        float ae = expf(g_u[s] + vt);
        float2 p = ((const float2*)g_P)[s * 32 + lane];
        acc.x += ae * fmaxf(p.x + c, 0.f);
        acc.y += ae * fmaxf(p.y + d, 0.f);
        asum  += ae;
    }
    float inv = 1.0f / (asum + EPSV);
    ((float2*)out)[t * 32 + lane] = make_float2(acc.x * inv, acc.y * inv);
    if (lane == 0) g_cnt[t] = 0;              // self-clean for next replay
}

// ---------------------------------------------------------------------------
extern "C" void kernel_launch(void* const* d_in, const int* in_sizes, int n_in,
                              void* d_out, int out_size) {
    const float* x   = (const float*)d_in[0];
    const float* src = (const float*)d_in[1];
    const float* tgt = (const float*)d_in[2];
    const float* Wf  = (const float*)d_in[3];
    const float* bf  = (const float*)d_in[4];
    const float* Ww  = (const float*)d_in[5];
    const float* bw  = (const float*)d_in[6];
    float* out = (float*)d_out;

    // side stream + events, created once on the (uncaptured) first call
    static cudaStream_t s2 = nullptr;
    static cudaEvent_t ev_fork = nullptr, ev_join = nullptr;
    if (s2 == nullptr) {
        cudaStreamCreateWithFlags(&s2, cudaStreamNonBlocking);
        cudaEventCreateWithFlags(&ev_fork, cudaEventDisableTiming);
        cudaEventCreateWithFlags(&ev_join, cudaEventDisableTiming);
    }

    // fork: k_pre (projections) overlaps the HBM-bound scan
    cudaEventRecord(ev_fork, 0);
    cudaStreamWaitEvent(s2, ev_fork, 0);
    k_pre<<<NODESN / 64, 256, 0, s2>>>(x, Wf, Ww);
    cudaEventRecord(ev_join, s2);

    k_scan<<<dim3(EDGES / 4 / 256, NODESN / RCHUNK), 256>>>(
        (const float4*)src, (const float4*)tgt);

    // join: gather needs scan (adjacency, g_si) and pre (P,Q,u,v)
    cudaStreamWaitEvent(0, ev_join, 0);
    k_gather<<<NODESN * 32 / 256, 256>>>(bf, bw, out);
}